// round 9
// baseline (speedup 1.0000x reference)
#include <cuda_runtime.h>
#include <cuda_bf16.h>
#include <math_constants.h>

// Problem constants
#define BB 16
#define CC 3
#define MM 512
#define NN 512
#define MNP (MM * NN)                 // 262144 pixels per (b, c) plane
#define PIX (BB * MNP)                // 4,194,304 pixels
#define PIX_PER_THREAD 4
#define THREADS1 256
#define BLOCKS1 (PIX / PIX_PER_THREAD / THREADS1)   // 4096
#define EPS_F 1e-6f
#define T1_CLIP_F 1e7f

// Fixed scratch for block partials (no allocation allowed)
__device__ float g_psum[BLOCKS1];
__device__ float g_pmax[BLOCKS1];
__device__ unsigned int g_count = 0;

// Single-MUFU approximate reciprocal (no Newton fixup). Max rel err ~2^-23.
__device__ __forceinline__ float rcp_approx(float x) {
    float y;
    asm("rcp.approx.f32 %0, %1;" : "=f"(y) : "f"(x));
    return y;
}

// Streaming 128-bit load (evict-first: one-pass data, don't pollute L2)
__device__ __forceinline__ float4 ldcs4(const float* p) {
    return __ldcs(reinterpret_cast<const float4*>(p));
}

__global__ __launch_bounds__(THREADS1) void maploss_main(
    const float* __restrict__ target,
    const float* __restrict__ mu,
    const float* __restrict__ sigma_y,
    float* __restrict__ out)
{
    const int t = blockIdx.x * THREADS1 + threadIdx.x;   // 0 .. PIX/4-1
    const int p0 = t * PIX_PER_THREAD;                   // first pixel
    const int b  = p0 >> 18;                             // / MNP
    const int r  = p0 & (MNP - 1);                       // offset within image

    // --- sigma_y: 9 contiguous floats/pixel, 4 pixels = 36 floats = 9 float4 ---
    float4 sv[9];
    const float* sybase = sigma_y + (size_t)p0 * 9;
#pragma unroll
    for (int i = 0; i < 9; i++) sv[i] = ldcs4(sybase + 4 * i);
    const float* sf = reinterpret_cast<const float*>(sv);

    // --- target - mu, per channel, 4 consecutive pixels each ---
    const size_t base = (size_t)b * (CC * MNP) + r;
    float4 t0 = ldcs4(target + base);
    float4 t1 = ldcs4(target + base + MNP);
    float4 t2 = ldcs4(target + base + 2 * MNP);
    float4 u0 = ldcs4(mu + base);
    float4 u1 = ldcs4(mu + base + MNP);
    float4 u2 = ldcs4(mu + base + 2 * MNP);

    float d0[4] = { t0.x - u0.x, t0.y - u0.y, t0.z - u0.z, t0.w - u0.w };
    float d1[4] = { t1.x - u1.x, t1.y - u1.y, t1.z - u1.z, t1.w - u1.w };
    float d2[4] = { t2.x - u2.x, t2.y - u2.y, t2.z - u2.z, t2.w - u2.w };

    float qv[4];   // quadratic forms (numerators, pre-division)
    float dc[4];   // clamped determinants

#pragma unroll
    for (int j = 0; j < 4; j++) {
        const float* s = sf + 9 * j;   // row-major 3x3, symmetric
        const float a  = s[0], bq = s[1], c = s[2];
        const float d  = s[4], e  = s[5];
        const float f  = s[8];

        // cofactors (adjugate of symmetric 3x3)
        const float A00 = fmaf(d, f, -e * e);
        const float A01 = fmaf(c, e, -bq * f);
        const float A02 = fmaf(bq, e, -c * d);
        const float A11 = fmaf(a, f, -c * c);
        const float A12 = fmaf(bq, c, -a * e);
        const float A22 = fmaf(a, d, -bq * bq);

        const float det = fmaf(a, A00, fmaf(bq, A01, c * A02));

        const float x = d0[j], y = d1[j], z = d2[j];
        float q = x * x * A00;
        q = fmaf(y * y, A11, q);
        q = fmaf(z * z, A22, q);
        float cross = x * y * A01;
        cross = fmaf(x * z, A02, cross);
        cross = fmaf(y * z, A12, cross);
        q = fmaf(2.0f, cross, q);

        qv[j] = q;
        dc[j] = fmaxf(det, EPS_F);   // SPD (>= 0.5 I) => clamp never binds
    }

    // --- batched reciprocal + batched log: 1 RCP + 1 LG2 per 4 pixels ---
    const float p01  = dc[0] * dc[1];
    const float p23  = dc[2] * dc[3];
    const float prod = p01 * p23;
    const float invp = rcp_approx(prod);

    const float i0 = dc[1] * p23 * invp;
    const float i1 = dc[0] * p23 * invp;
    const float i2 = p01 * dc[3] * invp;
    const float i3 = p01 * dc[2] * invp;

    const float t1v0 = 0.5f * qv[0] * i0;
    const float t1v1 = 0.5f * qv[1] * i1;
    const float t1v2 = 0.5f * qv[2] * i2;
    const float t1v3 = 0.5f * qv[3] * i3;

    // sum(0.5*log(dc_j)) = 0.5*log(prod)  (one MUFU.LG2)
    float sumv = (t1v0 + t1v1) + (t1v2 + t1v3) + 0.5f * __logf(prod);
    float maxv = fmaxf(fmaxf(t1v0, t1v1), fmaxf(t1v2, t1v3));

    // --- warp reduce ---
#pragma unroll
    for (int off = 16; off > 0; off >>= 1) {
        sumv += __shfl_down_sync(0xFFFFFFFFu, sumv, off);
        maxv  = fmaxf(maxv, __shfl_down_sync(0xFFFFFFFFu, maxv, off));
    }

    __shared__ float ssum[THREADS1 / 32];
    __shared__ float smax[THREADS1 / 32];
    const int lane = threadIdx.x & 31;
    const int wid  = threadIdx.x >> 5;
    if (lane == 0) { ssum[wid] = sumv; smax[wid] = maxv; }
    __syncthreads();

    if (wid == 0) {
        float s2 = (lane < THREADS1 / 32) ? ssum[lane] : 0.0f;
        float m2 = (lane < THREADS1 / 32) ? smax[lane] : -CUDART_INF_F;
#pragma unroll
        for (int off = 4; off > 0; off >>= 1) {
            s2 += __shfl_down_sync(0xFFFFFFFFu, s2, off);
            m2  = fmaxf(m2, __shfl_down_sync(0xFFFFFFFFu, m2, off));
        }
        if (lane == 0) {
            g_psum[blockIdx.x] = s2;
            g_pmax[blockIdx.x] = m2;
        }
    }

    // --- fused finish: last block to arrive reduces all partials ---
    __shared__ bool is_last;
    __syncthreads();            // ensure partial write issued before ticket
    if (threadIdx.x == 0) {
        __threadfence();        // make this block's partials globally visible
        unsigned int old = atomicAdd(&g_count, 1u);
        is_last = (old == (unsigned int)(BLOCKS1 - 1));
    }
    __syncthreads();

    if (is_last) {
        // 256 threads fold 4096 partials in a fixed order (deterministic).
        volatile float* ps = g_psum;
        volatile float* pm = g_pmax;
        float s = 0.0f;
        float m = -CUDART_INF_F;
#pragma unroll
        for (int i = 0; i < BLOCKS1 / THREADS1; i++) {
            const int idx = threadIdx.x + i * THREADS1;
            s += ps[idx];
            m  = fmaxf(m, pm[idx]);
        }
#pragma unroll
        for (int off = 16; off > 0; off >>= 1) {
            s += __shfl_down_sync(0xFFFFFFFFu, s, off);
            m  = fmaxf(m, __shfl_down_sync(0xFFFFFFFFu, m, off));
        }
        if (lane == 0) { ssum[wid] = s; smax[wid] = m; }
        __syncthreads();
        if (wid == 0) {
            float s2 = (lane < THREADS1 / 32) ? ssum[lane] : 0.0f;
            float m2 = (lane < THREADS1 / 32) ? smax[lane] : -CUDART_INF_F;
#pragma unroll
            for (int off = 4; off > 0; off >>= 1) {
                s2 += __shfl_down_sync(0xFFFFFFFFu, s2, off);
                m2  = fmaxf(m2, __shfl_down_sync(0xFFFFFFFFu, m2, off));
            }
            if (lane == 0) {
                const float mean = s2 * (1.0f / (float)PIX);
                out[0] = (m2 > T1_CLIP_F) ? 0.0f : mean;
                g_count = 0;   // reset ticket for next graph replay
            }
        }
    }
}

extern "C" void kernel_launch(void* const* d_in, const int* in_sizes, int n_in,
                              void* d_out, int out_size)
{
    // Input order per reference: target, mu, sigma_mu, sigma_n, sigma_y
    const float* target  = (const float*)d_in[0];
    const float* mu      = (const float*)d_in[1];
    const float* sigma_y = (const float*)d_in[4];
    float* out = (float*)d_out;

    maploss_main<<<BLOCKS1, THREADS1>>>(target, mu, sigma_y, out);
}

// round 10
// speedup vs baseline: 1.3048x; 1.3048x over previous
#include <cuda_runtime.h>
#include <cuda_bf16.h>
#include <math_constants.h>

// Problem constants
#define BB 16
#define CC 3
#define MM 512
#define NN 512
#define MNP (MM * NN)                 // 262144 pixels per (b, c) plane
#define PIX (BB * MNP)                // 4,194,304 pixels
#define THREADS1 256
#define PIX_PER_THREAD 4
#define PIX_PER_BLOCK (THREADS1 * PIX_PER_THREAD)     // 1024
#define BLOCKS1 (PIX / PIX_PER_BLOCK)                 // 4096
#define BLOCKS_PER_IMG (MNP / PIX_PER_BLOCK)          // 256
#define EPS_F 1e-6f
#define T1_CLIP_F 1e7f

// Fixed scratch for block partials (no allocation allowed)
__device__ float g_psum[BLOCKS1];
__device__ float g_pmax[BLOCKS1];
__device__ unsigned int g_count = 0;

// Single-MUFU approximate reciprocal (no Newton fixup).
__device__ __forceinline__ float rcp_approx(float x) {
    float y;
    asm("rcp.approx.f32 %0, %1;" : "=f"(y) : "f"(x));
    return y;
}

__global__ __launch_bounds__(THREADS1) void maploss_main(
    const float* __restrict__ target,
    const float* __restrict__ mu,
    const float* __restrict__ sigma_y,
    float* __restrict__ out)
{
    // Warp-owned sigma staging: 8 warps * 128 pixels * 9 floats = 9216 floats (36 KB)
    __shared__ float s_sig[THREADS1 * 9 * PIX_PER_THREAD];

    const int lane = threadIdx.x & 31;
    const int wid  = threadIdx.x >> 5;

    // Warp tile: 128 consecutive pixels
    const int warpPixBase = blockIdx.x * PIX_PER_BLOCK + wid * 128;

    // ---- 1) cp.async staging of sigma (coalesced, 16B chunks, L1-bypass) ----
    {
        const float* src = sigma_y + (size_t)warpPixBase * 9;   // 4608 B / warp
        unsigned smem_w = (unsigned)__cvta_generic_to_shared(
            &s_sig[wid * (128 * 9)]);
#pragma unroll
        for (int k = 0; k < 9; k++) {
            const int f4 = k * 32 + lane;                       // float4 index
            asm volatile("cp.async.cg.shared.global [%0], [%1], 16;"
                         :: "r"(smem_w + f4 * 16),
                            "l"(src + f4 * 4) : "memory");
        }
        asm volatile("cp.async.commit_group;" ::: "memory");
    }

    // ---- 2) target/mu: strided pixel assignment, scalar coalesced loads ----
    // Thread handles local pixels {lane, lane+32, lane+64, lane+96} of the warp tile.
    const int b = blockIdx.x >> 8;                              // / BLOCKS_PER_IMG
    const int rbase = (blockIdx.x & (BLOCKS_PER_IMG - 1)) * PIX_PER_BLOCK
                    + wid * 128 + lane;
    const size_t tbase = (size_t)b * (CC * MNP) + rbase;

    float dx[4], dy[4], dz[4];
#pragma unroll
    for (int j = 0; j < 4; j++) {
        const size_t o = tbase + j * 32;
        dx[j] = __ldcs(target + o)            - __ldcs(mu + o);
        dy[j] = __ldcs(target + o + MNP)      - __ldcs(mu + o + MNP);
        dz[j] = __ldcs(target + o + 2 * MNP)  - __ldcs(mu + o + 2 * MNP);
    }

    // ---- 3) wait for sigma, then per-pixel math from smem (conflict-free) ----
    asm volatile("cp.async.wait_group 0;" ::: "memory");
    __syncwarp();

    const float* sw = &s_sig[wid * (128 * 9)];

    float qv[4];   // quadratic-form numerators
    float dc[4];   // clamped determinants

#pragma unroll
    for (int j = 0; j < 4; j++) {
        const float* s = sw + (lane + j * 32) * 9;   // lane stride 9 words: no bank conflicts
        const float a  = s[0], bq = s[1], c = s[2];
        const float d  = s[4], e  = s[5];
        const float f  = s[8];

        // cofactors (adjugate of symmetric 3x3)
        const float A00 = fmaf(d, f, -e * e);
        const float A01 = fmaf(c, e, -bq * f);
        const float A02 = fmaf(bq, e, -c * d);
        const float A11 = fmaf(a, f, -c * c);
        const float A12 = fmaf(bq, c, -a * e);
        const float A22 = fmaf(a, d, -bq * bq);

        const float det = fmaf(a, A00, fmaf(bq, A01, c * A02));

        const float x = dx[j], y = dy[j], z = dz[j];
        float q = x * x * A00;
        q = fmaf(y * y, A11, q);
        q = fmaf(z * z, A22, q);
        float cross = x * y * A01;
        cross = fmaf(x * z, A02, cross);
        cross = fmaf(y * z, A12, cross);
        q = fmaf(2.0f, cross, q);

        qv[j] = q;
        dc[j] = fmaxf(det, EPS_F);   // SPD (>= 0.5 I) => clamp never binds
    }

    // ---- batched reciprocal + batched log: 1 RCP + 1 LG2 per 4 pixels ----
    const float p01  = dc[0] * dc[1];
    const float p23  = dc[2] * dc[3];
    const float prod = p01 * p23;
    const float invp = rcp_approx(prod);

    const float t1v0 = 0.5f * qv[0] * (dc[1] * p23 * invp);
    const float t1v1 = 0.5f * qv[1] * (dc[0] * p23 * invp);
    const float t1v2 = 0.5f * qv[2] * (p01 * dc[3] * invp);
    const float t1v3 = 0.5f * qv[3] * (p01 * dc[2] * invp);

    float sumv = (t1v0 + t1v1) + (t1v2 + t1v3) + 0.5f * __logf(prod);
    float maxv = fmaxf(fmaxf(t1v0, t1v1), fmaxf(t1v2, t1v3));

    // ---- warp reduce ----
#pragma unroll
    for (int off = 16; off > 0; off >>= 1) {
        sumv += __shfl_down_sync(0xFFFFFFFFu, sumv, off);
        maxv  = fmaxf(maxv, __shfl_down_sync(0xFFFFFFFFu, maxv, off));
    }

    __shared__ float ssum[THREADS1 / 32];
    __shared__ float smax[THREADS1 / 32];
    if (lane == 0) { ssum[wid] = sumv; smax[wid] = maxv; }
    __syncthreads();

    if (wid == 0) {
        float s2 = (lane < THREADS1 / 32) ? ssum[lane] : 0.0f;
        float m2 = (lane < THREADS1 / 32) ? smax[lane] : -CUDART_INF_F;
#pragma unroll
        for (int off = 4; off > 0; off >>= 1) {
            s2 += __shfl_down_sync(0xFFFFFFFFu, s2, off);
            m2  = fmaxf(m2, __shfl_down_sync(0xFFFFFFFFu, m2, off));
        }
        if (lane == 0) {
            g_psum[blockIdx.x] = s2;
            g_pmax[blockIdx.x] = m2;
        }
    }

    // ---- fused finish: last block reduces all partials ----
    __shared__ bool is_last;
    __syncthreads();
    if (threadIdx.x == 0) {
        __threadfence();        // publish this block's partials
        unsigned int old = atomicAdd(&g_count, 1u);
        is_last = (old == (unsigned int)(BLOCKS1 - 1));
    }
    __syncthreads();

    if (is_last) {
        if (threadIdx.x == 0) __threadfence();  // acquire: see all partials
        __syncthreads();
        // Batched, non-volatile L2 loads (MLP=16), fixed order => deterministic.
        float s = 0.0f;
        float m = -CUDART_INF_F;
#pragma unroll
        for (int i = 0; i < BLOCKS1 / THREADS1; i++) {
            const int idx = threadIdx.x + i * THREADS1;
            s += __ldcg(&g_psum[idx]);
            m  = fmaxf(m, __ldcg(&g_pmax[idx]));
        }
#pragma unroll
        for (int off = 16; off > 0; off >>= 1) {
            s += __shfl_down_sync(0xFFFFFFFFu, s, off);
            m  = fmaxf(m, __shfl_down_sync(0xFFFFFFFFu, m, off));
        }
        if (lane == 0) { ssum[wid] = s; smax[wid] = m; }
        __syncthreads();
        if (wid == 0) {
            float s2 = (lane < THREADS1 / 32) ? ssum[lane] : 0.0f;
            float m2 = (lane < THREADS1 / 32) ? smax[lane] : -CUDART_INF_F;
#pragma unroll
            for (int off = 4; off > 0; off >>= 1) {
                s2 += __shfl_down_sync(0xFFFFFFFFu, s2, off);
                m2  = fmaxf(m2, __shfl_down_sync(0xFFFFFFFFu, m2, off));
            }
            if (lane == 0) {
                const float mean = s2 * (1.0f / (float)PIX);
                out[0] = (m2 > T1_CLIP_F) ? 0.0f : mean;
                g_count = 0;   // reset ticket for next graph replay
            }
        }
    }
}

extern "C" void kernel_launch(void* const* d_in, const int* in_sizes, int n_in,
                              void* d_out, int out_size)
{
    // Input order per reference: target, mu, sigma_mu, sigma_n, sigma_y
    const float* target  = (const float*)d_in[0];
    const float* mu      = (const float*)d_in[1];
    const float* sigma_y = (const float*)d_in[4];
    float* out = (float*)d_out;

    maploss_main<<<BLOCKS1, THREADS1>>>(target, mu, sigma_y, out);
}